// round 4
// baseline (speedup 1.0000x reference)
#include <cuda_runtime.h>
#include <cstdint>

#define NN 8192
#define DD 128
#define KNN 20
#define NC 10
#define NW 256    // 32-bit words per mask row
#define HB 2048   // histogram bins
#define BCAP 256  // boundary candidate capacity

// ---------------- scratch (device globals; no allocations) ----------------
__device__ float        g_dist[(size_t)NN * NN];   // squared distances (clamped >= 0)
__device__ float        g_sq[NN];
__device__ float        g_density[NN];
__device__ unsigned int g_mask[(size_t)NN * NW];   // kmask | kmask^T

// ---------------- kernel 1: zero the mask ----------------
__global__ void zero_mask_kernel() {
    int i = blockIdx.x * blockDim.x + threadIdx.x;
    if (i < NN * NW) g_mask[i] = 0u;
}

// ---------------- kernel 2: row squared norms ----------------
__global__ void norms_kernel(const float* __restrict__ X) {
    int row  = blockIdx.x * 8 + (threadIdx.x >> 5);
    int lane = threadIdx.x & 31;
    const float4* xr = (const float4*)(X + (size_t)row * DD);
    float4 v = xr[lane];
    float s = v.x * v.x + v.y * v.y + v.z * v.z + v.w * v.w;
#pragma unroll
    for (int o = 16; o; o >>= 1) s += __shfl_xor_sync(0xffffffffu, s, o);
    if (lane == 0) g_sq[row] = s;
}

// ---------------- kernel 3: symmetric tiled squared-distance matrix -------
__global__ __launch_bounds__(256) void dist_kernel(const float* __restrict__ X) {
    int bi = blockIdx.y, bj = blockIdx.x;
    if (bj < bi) return;

    __shared__ __align__(16) float smem[64 * 68];
    float* AsT = smem;
    float* BsT = smem + 32 * 68;

    int tid = threadIdx.x;
    int tx = tid & 15, ty = tid >> 4;

    float acc[4][4];
#pragma unroll
    for (int a = 0; a < 4; a++)
#pragma unroll
        for (int b = 0; b < 4; b++) acc[a][b] = 0.f;

    const float* Arow = X + (size_t)(bi * 64) * DD;
    const float* Brow = X + (size_t)(bj * 64) * DD;

    for (int kb = 0; kb < DD; kb += 32) {
#pragma unroll
        for (int u = 0; u < 2; u++) {
            int f  = tid + u * 256;
            int r  = f >> 3;
            int c4 = (f & 7) * 4;
            float4 va = *(const float4*)(Arow + (size_t)r * DD + kb + c4);
            AsT[(c4 + 0) * 68 + r] = va.x;
            AsT[(c4 + 1) * 68 + r] = va.y;
            AsT[(c4 + 2) * 68 + r] = va.z;
            AsT[(c4 + 3) * 68 + r] = va.w;
            float4 vb = *(const float4*)(Brow + (size_t)r * DD + kb + c4);
            BsT[(c4 + 0) * 68 + r] = vb.x;
            BsT[(c4 + 1) * 68 + r] = vb.y;
            BsT[(c4 + 2) * 68 + r] = vb.z;
            BsT[(c4 + 3) * 68 + r] = vb.w;
        }
        __syncthreads();
#pragma unroll
        for (int k = 0; k < 32; k++) {
            float4 a4 = *(const float4*)&AsT[k * 68 + ty * 4];
            float4 b4 = *(const float4*)&BsT[k * 68 + tx * 4];
            acc[0][0] += a4.x * b4.x; acc[0][1] += a4.x * b4.y; acc[0][2] += a4.x * b4.z; acc[0][3] += a4.x * b4.w;
            acc[1][0] += a4.y * b4.x; acc[1][1] += a4.y * b4.y; acc[1][2] += a4.y * b4.z; acc[1][3] += a4.y * b4.w;
            acc[2][0] += a4.z * b4.x; acc[2][1] += a4.z * b4.y; acc[2][2] += a4.z * b4.z; acc[2][3] += a4.z * b4.w;
            acc[3][0] += a4.w * b4.x; acc[3][1] += a4.w * b4.y; acc[3][2] += a4.w * b4.z; acc[3][3] += a4.w * b4.w;
        }
        __syncthreads();
    }

    float sa[4], sb[4];
#pragma unroll
    for (int a = 0; a < 4; a++) sa[a] = g_sq[bi * 64 + ty * 4 + a];
#pragma unroll
    for (int b = 0; b < 4; b++) sb[b] = g_sq[bj * 64 + tx * 4 + b];

#pragma unroll
    for (int a = 0; a < 4; a++) {
        int R = bi * 64 + ty * 4 + a;
        float4 o;
        o.x = fmaxf(sa[a] + sb[0] - 2.f * acc[a][0], 0.f);
        o.y = fmaxf(sa[a] + sb[1] - 2.f * acc[a][1], 0.f);
        o.z = fmaxf(sa[a] + sb[2] - 2.f * acc[a][2], 0.f);
        o.w = fmaxf(sa[a] + sb[3] - 2.f * acc[a][3], 0.f);
        *(float4*)(g_dist + (size_t)R * NN + bj * 64 + tx * 4) = o;
        acc[a][0] = o.x; acc[a][1] = o.y; acc[a][2] = o.z; acc[a][3] = o.w;
    }

    if (bi != bj) {
        float* T = smem;
#pragma unroll
        for (int a = 0; a < 4; a++)
#pragma unroll
            for (int b = 0; b < 4; b++)
                T[(tx * 4 + b) * 68 + (ty * 4 + a)] = acc[a][b];
        __syncthreads();
#pragma unroll
        for (int a = 0; a < 4; a++) {
            int R = bj * 64 + ty * 4 + a;
            float4 o = *(const float4*)&T[(ty * 4 + a) * 68 + tx * 4];
            *(float4*)(g_dist + (size_t)R * NN + bi * 64 + tx * 4) = o;
        }
    }
}

// ---------------- helpers for topk ----------------
__device__ __forceinline__ void hist_add(int* hist, unsigned bin) {
    // warp-aggregated smem atomic: one atomicAdd per distinct bin per warp
    unsigned peers = __match_any_sync(0xffffffffu, bin);
    int leader = __ffs(peers) - 1;
    if ((int)(threadIdx.x & 31) == leader)
        atomicAdd(&hist[bin], __popc(peers));
}

// block-wide: find bin B s.t. cum(<B) < target <= cum(<=B); also below=cum(<B)
// hist has HB bins; each thread owns 8. Results in *s_B / *s_below.
__device__ __forceinline__ void find_pivot(int* hist, int* wsum, int target,
                                           int* s_B, int* s_below) {
    int tid = threadIdx.x, lane = tid & 31, wid = tid >> 5;
    int p = 0;
#pragma unroll
    for (int q = 0; q < 8; q++) p += hist[tid * 8 + q];
    int v = p;
#pragma unroll
    for (int o = 1; o < 32; o <<= 1) {
        int n = __shfl_up_sync(0xffffffffu, v, o);
        if (lane >= o) v += n;
    }
    if (lane == 31) wsum[wid] = v;
    __syncthreads();
    if (tid < 8) {
        int w = wsum[tid];
#pragma unroll
        for (int o = 1; o < 8; o <<= 1) {
            int n = __shfl_up_sync(0xffu, w, o);
            if (tid >= o) w += n;
        }
        wsum[tid] = w;
    }
    __syncthreads();
    int incl = v + (wid ? wsum[wid - 1] : 0);
    int excl = incl - p;
    if (excl < target && incl >= target) {
        int c = excl, B = 0;
        for (int q = 0; q < 8; q++) {
            int h = hist[tid * 8 + q];
            if (c + h >= target) { B = tid * 8 + q; break; }
            c += h;
        }
        *s_B = B;
        *s_below = c;
    }
    __syncthreads();
}

// ---------------- kernel 4: per-row top-K, two-level radix select ---------
__global__ __launch_bounds__(256) void topk_kernel() {
    int i = blockIdx.x, tid = threadIdx.x;
    int lane = tid & 31, wid = tid >> 5;

    __shared__ __align__(16) float sd[NN];            // 32 KB row of d^2
    __shared__ int hist[HB];                          // 8 KB
    __shared__ unsigned long long bnd[BCAP];          // 2 KB
    __shared__ unsigned long long cand[32];
    __shared__ int wsum[8];
    __shared__ int s_B1, s_below1, s_B2, s_below2, n_cand, n_bnd;

    for (int j = tid; j < HB; j += 256) hist[j] = 0;
    if (tid == 0) { n_cand = 0; n_bnd = 0; }
    __syncthreads();

    // load row + level-1 histogram (bits >> 20), warp-aggregated
    const float4* r4 = (const float4*)(g_dist + (size_t)i * NN);
    float4* s4 = (float4*)sd;
#pragma unroll
    for (int u = 0; u < 8; u++) {
        int j = tid + 256 * u;
        float4 v = r4[j];
        s4[j] = v;
        hist_add(hist, __float_as_uint(v.x) >> 20);
        hist_add(hist, __float_as_uint(v.y) >> 20);
        hist_add(hist, __float_as_uint(v.z) >> 20);
        hist_add(hist, __float_as_uint(v.w) >> 20);
    }
    __syncthreads();

    find_pivot(hist, wsum, KNN, &s_B1, &s_below1);
    unsigned B1 = (unsigned)s_B1;
    int below1 = s_below1;

    // zero hist for level 2
    for (int j = tid; j < HB; j += 256) hist[j] = 0;
    __syncthreads();

    // level-2 histogram: elements in bin B1, keyed by next 11 bits
#pragma unroll
    for (int u = 0; u < 32; u++) {
        int j = tid + 256 * u;
        unsigned bb = __float_as_uint(sd[j]);
        if ((bb >> 20) == B1) atomicAdd(&hist[(bb >> 9) & 0x7FF], 1);
    }
    __syncthreads();

    find_pivot(hist, wsum, KNN - below1, &s_B2, &s_below2);
    unsigned B2 = (unsigned)s_B2;
    int below2 = s_below2;

    // collect: definite members -> cand, boundary sub-bin -> bnd
#pragma unroll
    for (int u = 0; u < 32; u++) {
        int j = tid + 256 * u;
        unsigned bb = __float_as_uint(sd[j]);
        unsigned b1 = bb >> 20;
        if (b1 > B1) continue;
        unsigned long long key = ((unsigned long long)bb << 32) | (unsigned)j;
        if (b1 < B1) {
            cand[atomicAdd(&n_cand, 1)] = key;        // below1 < 20
        } else {
            unsigned b2 = (bb >> 9) & 0x7FF;
            if (b2 < B2) {
                cand[atomicAdd(&n_cand, 1)] = key;    // below1+below2 < 20
            } else if (b2 == B2) {
                int pos = atomicAdd(&n_bnd, 1);
                if (pos < BCAP) bnd[pos] = key;
            }
        }
    }
    __syncthreads();

    // warp 0: pick remaining from boundary sub-bin + finish row
    if (wid == 0) {
        int have = below1 + below2;
        int need = KNN - have;
        int nb   = n_bnd;
        if (nb <= BCAP) {
            for (int t = 0; t < need; t++) {
                unsigned long long m = 0xFFFFFFFFFFFFFFFFull;
                for (int j = lane; j < nb; j += 32) {
                    unsigned long long k = bnd[j];
                    if (k < m) m = k;
                }
#pragma unroll
                for (int o = 16; o; o >>= 1) {
                    unsigned long long oth = __shfl_xor_sync(0xffffffffu, m, o);
                    if (oth < m) m = oth;
                }
                for (int j = lane; j < nb; j += 32)
                    if (bnd[j] == m) bnd[j] = 0xFFFFFFFFFFFFFFFFull;
                if (lane == 0) cand[have + t] = m;
            }
        } else {
            // fallback: iterative select within (B1,B2) over full row
            unsigned long long last = 0;
            for (int t = 0; t < need; t++) {
                unsigned long long m = 0xFFFFFFFFFFFFFFFFull;
                for (int j = lane; j < NN; j += 32) {
                    unsigned bb = __float_as_uint(sd[j]);
                    if ((bb >> 20) == B1 && ((bb >> 9) & 0x7FF) == B2) {
                        unsigned long long key =
                            ((unsigned long long)bb << 32) | (unsigned)j;
                        if ((t == 0 || key > last) && key < m) m = key;
                    }
                }
#pragma unroll
                for (int o = 16; o; o >>= 1) {
                    unsigned long long oth = __shfl_xor_sync(0xffffffffu, m, o);
                    if (oth < m) m = oth;
                }
                last = m;
                if (lane == 0) cand[have + t] = m;
            }
        }
        __syncwarp();

        float d = 0.f;
        if (lane < KNN) {
            unsigned long long k = cand[lane];
            int idx = (int)(k & 0xFFFFFFFFull);
            d = sqrtf(__uint_as_float((unsigned)(k >> 32)));
            atomicOr(&g_mask[(size_t)i * NW + (idx >> 5)], 1u << (idx & 31));
            atomicOr(&g_mask[(size_t)idx * NW + (i >> 5)], 1u << (i & 31));
        }
#pragma unroll
        for (int o = 16; o; o >>= 1) d += __shfl_xor_sync(0xffffffffu, d, o);
        if (lane == 0)
            g_density[i] = 1.0f / (d / (float)KNN + 1e-10f);
    }
}

// ---------------- kernel 5: influence average + score + classify ----------
__global__ void final_kernel(const float* __restrict__ logits,
                             float* __restrict__ out, int out_size) {
    int row  = blockIdx.x * 8 + (threadIdx.x >> 5);
    int lane = threadIdx.x & 31;
    const unsigned int* mr = g_mask + (size_t)row * NW;

    float s = 0.f;
    int cnt = 0;
#pragma unroll
    for (int u = 0; u < 8; u++) {
        int w = lane + 32 * u;
        unsigned int bits = mr[w];
        cnt += __popc(bits);
        while (bits) {
            int b = __ffs(bits) - 1;
            bits &= bits - 1;
            s += g_density[w * 32 + b];
        }
    }
#pragma unroll
    for (int o = 16; o; o >>= 1) {
        s   += __shfl_xor_sync(0xffffffffu, s, o);
        cnt += __shfl_xor_sync(0xffffffffu, cnt, o);
    }
    if (lane == 0) {
        float den   = g_density[row];
        float avg   = s / (float)(cnt > 0 ? cnt : 1);
        float score = -(den / (avg + 1e-10f));
        out[row] = score;
        bool flag = score < -0.5f;
        if (out_size >= 2 * NN) out[NN + row] = flag ? 1.f : 0.f;
        if (out_size >= 3 * NN) {
            int pred = -1;
            if (!flag) {
                const float* lg = logits + (size_t)row * NC;
                float best = lg[0]; pred = 0;
#pragma unroll
                for (int c = 1; c < NC; c++)
                    if (lg[c] > best) { best = lg[c]; pred = c; }
            }
            out[2 * NN + row] = (float)pred;
        }
    }
}

// ---------------- launch ----------------
extern "C" void kernel_launch(void* const* d_in, const int* in_sizes, int n_in,
                              void* d_out, int out_size) {
    (void)in_sizes; (void)n_in;
    const float* X = (const float*)d_in[0];   // embeddings [8192,128] f32
    const float* L = (const float*)d_in[1];   // logits     [8192,10]  f32
    float* out = (float*)d_out;

    zero_mask_kernel<<<(NN * NW + 255) / 256, 256>>>();
    norms_kernel<<<NN / 8, 256>>>(X);
    dim3 g(NN / 64, NN / 64);
    dist_kernel<<<g, 256>>>(X);
    topk_kernel<<<NN, 256>>>();
    final_kernel<<<NN / 8, 256>>>(L, out, out_size);
}

// round 5
// speedup vs baseline: 1.4419x; 1.4419x over previous
#include <cuda_runtime.h>
#include <cuda_bf16.h>
#include <cstdint>

#define NN 8192
#define DD 128
#define KNN 20
#define NC 10
#define NW 256    // 32-bit words per mask row
#define HB 2048   // histogram bins
#define BCAP 256  // boundary candidate capacity
#define KC 32     // K-chunk for dist tiles
#define TSTR 40   // smem tile row stride in bf16 (conflict-free: 20 u32)

// ---------------- scratch (device globals; no allocations) ----------------
__device__ float          g_dist[(size_t)NN * NN];   // squared distances
__device__ float          g_sq[NN];
__device__ float          g_density[NN];
__device__ unsigned int   g_mask[(size_t)NN * NW];
__device__ __nv_bfloat16  g_Xhi[(size_t)NN * DD];
__device__ __nv_bfloat16  g_Xlo[(size_t)NN * DD];

// ---------------- kernel 1: zero the mask ----------------
__global__ void zero_mask_kernel() {
    int i = blockIdx.x * blockDim.x + threadIdx.x;
    if (i < NN * NW) g_mask[i] = 0u;
}

// ---------------- kernel 2: split X -> bf16 hi/lo + row norms -------------
__global__ void prep_kernel(const float* __restrict__ X) {
    int row  = blockIdx.x * 8 + (threadIdx.x >> 5);
    int lane = threadIdx.x & 31;
    float4 v = ((const float4*)(X + (size_t)row * DD))[lane];

    __nv_bfloat16 h0 = __float2bfloat16(v.x);
    __nv_bfloat16 h1 = __float2bfloat16(v.y);
    __nv_bfloat16 h2 = __float2bfloat16(v.z);
    __nv_bfloat16 h3 = __float2bfloat16(v.w);
    __nv_bfloat16 l0 = __float2bfloat16(v.x - __bfloat162float(h0));
    __nv_bfloat16 l1 = __float2bfloat16(v.y - __bfloat162float(h1));
    __nv_bfloat16 l2 = __float2bfloat16(v.z - __bfloat162float(h2));
    __nv_bfloat16 l3 = __float2bfloat16(v.w - __bfloat162float(h3));

    uint2 ph, pl;
    ph.x = ((unsigned)__bfloat16_as_ushort(h1) << 16) | __bfloat16_as_ushort(h0);
    ph.y = ((unsigned)__bfloat16_as_ushort(h3) << 16) | __bfloat16_as_ushort(h2);
    pl.x = ((unsigned)__bfloat16_as_ushort(l1) << 16) | __bfloat16_as_ushort(l0);
    pl.y = ((unsigned)__bfloat16_as_ushort(l3) << 16) | __bfloat16_as_ushort(l2);
    ((uint2*)g_Xhi)[(size_t)row * 32 + lane] = ph;
    ((uint2*)g_Xlo)[(size_t)row * 32 + lane] = pl;

    float s = v.x * v.x + v.y * v.y + v.z * v.z + v.w * v.w;
#pragma unroll
    for (int o = 16; o; o >>= 1) s += __shfl_xor_sync(0xffffffffu, s, o);
    if (lane == 0) g_sq[row] = s;
}

// ---------------- mma.sync helper ----------------
__device__ __forceinline__ void mma_bf16(float* c, const unsigned* a,
                                         unsigned b0, unsigned b1) {
    asm volatile(
        "mma.sync.aligned.m16n8k16.row.col.f32.bf16.bf16.f32 "
        "{%0,%1,%2,%3}, {%4,%5,%6,%7}, {%8,%9}, {%0,%1,%2,%3};"
        : "+f"(c[0]), "+f"(c[1]), "+f"(c[2]), "+f"(c[3])
        : "r"(a[0]), "r"(a[1]), "r"(a[2]), "r"(a[3]), "r"(b0), "r"(b1));
}

// ---------------- kernel 3: tensor-core squared-distance matrix -----------
// Full matrix (no symmetry), 128x128 block tile, 8 warps (4x2), each warp
// 32(M)x64(N). Split-bf16: dot = hi.hi + hi.lo + lo.hi, fp32 accumulate.
__global__ __launch_bounds__(256) void dist_tc_kernel() {
    int bi = blockIdx.y, bj = blockIdx.x;
    int row0 = bi * 128, col0 = bj * 128;

    __shared__ __align__(16) __nv_bfloat16 smem[4 * 128 * TSTR];  // 40 KB
    __nv_bfloat16* Ahi = smem;
    __nv_bfloat16* Alo = smem + 128 * TSTR;
    __nv_bfloat16* Bhi = smem + 2 * 128 * TSTR;
    __nv_bfloat16* Blo = smem + 3 * 128 * TSTR;

    int tid  = threadIdx.x;
    int w    = tid >> 5, lane = tid & 31;
    int wm   = w & 3,    wn   = w >> 2;    // warp tile: M [wm*32,+32), N [wn*64,+64)
    int g    = lane >> 2, tig = lane & 3;

    float C[2][8][4];
#pragma unroll
    for (int mt = 0; mt < 2; mt++)
#pragma unroll
        for (int nt = 0; nt < 8; nt++)
#pragma unroll
            for (int q = 0; q < 4; q++) C[mt][nt][q] = 0.f;

    for (int kb = 0; kb < DD; kb += KC) {
        // load 128x32 hi/lo tiles for A-rows and B-rows (uint4 = 8 bf16)
#pragma unroll
        for (int u = 0; u < 2; u++) {
            int idx = tid + u * 256;           // 0..511
            int r   = idx >> 2;
            int c8  = (idx & 3) * 8;
            size_t goA = (size_t)(row0 + r) * DD + kb + c8;
            size_t goB = (size_t)(col0 + r) * DD + kb + c8;
            *(uint4*)&Ahi[r * TSTR + c8] = *(const uint4*)&g_Xhi[goA];
            *(uint4*)&Alo[r * TSTR + c8] = *(const uint4*)&g_Xlo[goA];
            *(uint4*)&Bhi[r * TSTR + c8] = *(const uint4*)&g_Xhi[goB];
            *(uint4*)&Blo[r * TSTR + c8] = *(const uint4*)&g_Xlo[goB];
        }
        __syncthreads();

#pragma unroll
        for (int ks = 0; ks < KC; ks += 16) {
            unsigned ahi[2][4], alo[2][4];
#pragma unroll
            for (int mt = 0; mt < 2; mt++) {
                int br = wm * 32 + mt * 16;
                int o0 = (br + g) * TSTR + ks + tig * 2;
                int o1 = (br + g + 8) * TSTR + ks + tig * 2;
                ahi[mt][0] = *(const unsigned*)&Ahi[o0];
                ahi[mt][1] = *(const unsigned*)&Ahi[o1];
                ahi[mt][2] = *(const unsigned*)&Ahi[o0 + 8];
                ahi[mt][3] = *(const unsigned*)&Ahi[o1 + 8];
                alo[mt][0] = *(const unsigned*)&Alo[o0];
                alo[mt][1] = *(const unsigned*)&Alo[o1];
                alo[mt][2] = *(const unsigned*)&Alo[o0 + 8];
                alo[mt][3] = *(const unsigned*)&Alo[o1 + 8];
            }
#pragma unroll
            for (int nt = 0; nt < 8; nt++) {
                int bn = wn * 64 + nt * 8 + g;
                int ob = bn * TSTR + ks + tig * 2;
                unsigned bh0 = *(const unsigned*)&Bhi[ob];
                unsigned bh1 = *(const unsigned*)&Bhi[ob + 8];
                unsigned bl0 = *(const unsigned*)&Blo[ob];
                unsigned bl1 = *(const unsigned*)&Blo[ob + 8];
#pragma unroll
                for (int mt = 0; mt < 2; mt++) {
                    mma_bf16(C[mt][nt], ahi[mt], bh0, bh1);
                    mma_bf16(C[mt][nt], ahi[mt], bl0, bl1);
                    mma_bf16(C[mt][nt], alo[mt], bh0, bh1);
                }
            }
        }
        __syncthreads();
    }

    // epilogue: d2 = sa + sb - 2*dot, clamped; coalesced-ish float2 stores
    float sb0[8], sb1[8];
#pragma unroll
    for (int nt = 0; nt < 8; nt++) {
        int n = col0 + wn * 64 + nt * 8 + tig * 2;
        sb0[nt] = g_sq[n];
        sb1[nt] = g_sq[n + 1];
    }
#pragma unroll
    for (int mt = 0; mt < 2; mt++) {
        int m0 = row0 + wm * 32 + mt * 16;
        float saA = g_sq[m0 + g];
        float saB = g_sq[m0 + g + 8];
#pragma unroll
        for (int nt = 0; nt < 8; nt++) {
            int n = col0 + wn * 64 + nt * 8 + tig * 2;
            float2 oA, oB;
            oA.x = fmaxf(saA + sb0[nt] - 2.f * C[mt][nt][0], 0.f);
            oA.y = fmaxf(saA + sb1[nt] - 2.f * C[mt][nt][1], 0.f);
            oB.x = fmaxf(saB + sb0[nt] - 2.f * C[mt][nt][2], 0.f);
            oB.y = fmaxf(saB + sb1[nt] - 2.f * C[mt][nt][3], 0.f);
            *(float2*)(g_dist + (size_t)(m0 + g) * NN + n)     = oA;
            *(float2*)(g_dist + (size_t)(m0 + g + 8) * NN + n) = oB;
        }
    }
}

// ---------------- kernel 4: per-row top-K, single-level histogram select --
// R3 structure, but no smem row staging (pass 2 re-reads row from L2).
__global__ __launch_bounds__(256) void topk_kernel() {
    int i = blockIdx.x, tid = threadIdx.x;
    int lane = tid & 31, wid = tid >> 5;

    __shared__ int hist[HB];                          // 8 KB
    __shared__ unsigned long long bnd[BCAP];          // 2 KB
    __shared__ unsigned long long cand[32];
    __shared__ int wsum[8];
    __shared__ int s_pivot, s_below, n_cand, n_bnd;

    for (int j = tid; j < HB; j += 256) hist[j] = 0;
    if (tid == 0) { n_cand = 0; n_bnd = 0; }
    __syncthreads();

    const float4* r4 = (const float4*)(g_dist + (size_t)i * NN);

    // pass 1: histogram of float bits >> 20 (valid order: all values >= 0)
#pragma unroll
    for (int u = 0; u < 8; u++) {
        float4 v = r4[tid + 256 * u];
        atomicAdd(&hist[__float_as_uint(v.x) >> 20], 1);
        atomicAdd(&hist[__float_as_uint(v.y) >> 20], 1);
        atomicAdd(&hist[__float_as_uint(v.z) >> 20], 1);
        atomicAdd(&hist[__float_as_uint(v.w) >> 20], 1);
    }
    __syncthreads();

    // block prefix scan over per-thread partials -> pivot bin
    int p = 0;
#pragma unroll
    for (int q = 0; q < 8; q++) p += hist[tid * 8 + q];
    int v = p;
#pragma unroll
    for (int o = 1; o < 32; o <<= 1) {
        int n = __shfl_up_sync(0xffffffffu, v, o);
        if (lane >= o) v += n;
    }
    if (lane == 31) wsum[wid] = v;
    __syncthreads();
    if (tid < 8) {
        int w = wsum[tid];
#pragma unroll
        for (int o = 1; o < 8; o <<= 1) {
            int n = __shfl_up_sync(0xffu, w, o);
            if (tid >= o) w += n;
        }
        wsum[tid] = w;
    }
    __syncthreads();
    int incl = v + (wid ? wsum[wid - 1] : 0);
    int excl = incl - p;
    if (excl < KNN && incl >= KNN) {
        int c = excl, B = 0;
        for (int q = 0; q < 8; q++) {
            int h = hist[tid * 8 + q];
            if (c + h >= KNN) { B = tid * 8 + q; break; }
            c += h;
        }
        s_pivot = B;
        s_below = c;
    }
    __syncthreads();

    // pass 2 (L2-hot): collect below-pivot + boundary-bin candidates
    unsigned B = (unsigned)s_pivot;
#pragma unroll
    for (int u = 0; u < 8; u++) {
        int j4 = tid + 256 * u;
        float4 vv = r4[j4];
        float elem[4] = {vv.x, vv.y, vv.z, vv.w};
#pragma unroll
        for (int q = 0; q < 4; q++) {
            unsigned bb = __float_as_uint(elem[q]);
            unsigned bin = bb >> 20;
            if (bin <= B) {
                int j = j4 * 4 + q;
                unsigned long long key =
                    ((unsigned long long)bb << 32) | (unsigned)j;
                if (bin < B) {
                    cand[atomicAdd(&n_cand, 1)] = key;     // guaranteed < 20
                } else {
                    int pos = atomicAdd(&n_bnd, 1);
                    if (pos < BCAP) bnd[pos] = key;
                }
            }
        }
    }
    __syncthreads();

    // warp 0: exact selection from boundary bin + finish row
    if (wid == 0) {
        int below = s_below;
        int need  = KNN - below;
        int nb    = n_bnd;
        if (nb <= BCAP) {
            for (int t = 0; t < need; t++) {
                unsigned long long m = 0xFFFFFFFFFFFFFFFFull;
                for (int j = lane; j < nb; j += 32) {
                    unsigned long long k = bnd[j];
                    if (k < m) m = k;
                }
#pragma unroll
                for (int o = 16; o; o >>= 1) {
                    unsigned long long oth = __shfl_xor_sync(0xffffffffu, m, o);
                    if (oth < m) m = oth;
                }
                for (int j = lane; j < nb; j += 32)
                    if (bnd[j] == m) bnd[j] = 0xFFFFFFFFFFFFFFFFull;
                if (lane == 0) cand[below + t] = m;
            }
        } else {
            // fallback: iterative select within pivot bin over global row
            const float* row = g_dist + (size_t)i * NN;
            unsigned long long last = 0;
            for (int t = 0; t < need; t++) {
                unsigned long long m = 0xFFFFFFFFFFFFFFFFull;
                for (int j = lane; j < NN; j += 32) {
                    unsigned bb = __float_as_uint(row[j]);
                    if ((bb >> 20) == B) {
                        unsigned long long key =
                            ((unsigned long long)bb << 32) | (unsigned)j;
                        if ((t == 0 || key > last) && key < m) m = key;
                    }
                }
#pragma unroll
                for (int o = 16; o; o >>= 1) {
                    unsigned long long oth = __shfl_xor_sync(0xffffffffu, m, o);
                    if (oth < m) m = oth;
                }
                last = m;
                if (lane == 0) cand[below + t] = m;
            }
        }
        __syncwarp();

        float d = 0.f;
        if (lane < KNN) {
            unsigned long long k = cand[lane];
            int idx = (int)(k & 0xFFFFFFFFull);
            d = sqrtf(__uint_as_float((unsigned)(k >> 32)));
            atomicOr(&g_mask[(size_t)i * NW + (idx >> 5)], 1u << (idx & 31));
            atomicOr(&g_mask[(size_t)idx * NW + (i >> 5)], 1u << (i & 31));
        }
#pragma unroll
        for (int o = 16; o; o >>= 1) d += __shfl_xor_sync(0xffffffffu, d, o);
        if (lane == 0)
            g_density[i] = 1.0f / (d / (float)KNN + 1e-10f);
    }
}

// ---------------- kernel 5: influence average + score + classify ----------
__global__ void final_kernel(const float* __restrict__ logits,
                             float* __restrict__ out, int out_size) {
    int row  = blockIdx.x * 8 + (threadIdx.x >> 5);
    int lane = threadIdx.x & 31;
    const unsigned int* mr = g_mask + (size_t)row * NW;

    float s = 0.f;
    int cnt = 0;
#pragma unroll
    for (int u = 0; u < 8; u++) {
        int w = lane + 32 * u;
        unsigned int bits = mr[w];
        cnt += __popc(bits);
        while (bits) {
            int b = __ffs(bits) - 1;
            bits &= bits - 1;
            s += g_density[w * 32 + b];
        }
    }
#pragma unroll
    for (int o = 16; o; o >>= 1) {
        s   += __shfl_xor_sync(0xffffffffu, s, o);
        cnt += __shfl_xor_sync(0xffffffffu, cnt, o);
    }
    if (lane == 0) {
        float den   = g_density[row];
        float avg   = s / (float)(cnt > 0 ? cnt : 1);
        float score = -(den / (avg + 1e-10f));
        out[row] = score;
        bool flag = score < -0.5f;
        if (out_size >= 2 * NN) out[NN + row] = flag ? 1.f : 0.f;
        if (out_size >= 3 * NN) {
            int pred = -1;
            if (!flag) {
                const float* lg = logits + (size_t)row * NC;
                float best = lg[0]; pred = 0;
#pragma unroll
                for (int c = 1; c < NC; c++)
                    if (lg[c] > best) { best = lg[c]; pred = c; }
            }
            out[2 * NN + row] = (float)pred;
        }
    }
}

// ---------------- launch ----------------
extern "C" void kernel_launch(void* const* d_in, const int* in_sizes, int n_in,
                              void* d_out, int out_size) {
    (void)in_sizes; (void)n_in;
    const float* X = (const float*)d_in[0];   // embeddings [8192,128] f32
    const float* L = (const float*)d_in[1];   // logits     [8192,10]  f32
    float* out = (float*)d_out;

    zero_mask_kernel<<<(NN * NW + 255) / 256, 256>>>();
    prep_kernel<<<NN / 8, 256>>>(X);
    dim3 g(NN / 128, NN / 128);
    dist_tc_kernel<<<g, 256>>>();
    topk_kernel<<<NN, 256>>>();
    final_kernel<<<NN / 8, 256>>>(L, out, out_size);
}